// round 5
// baseline (speedup 1.0000x reference)
#include <cuda_runtime.h>
#include <cuda_bf16.h>
#include <cstdint>
#include <math.h>

#define Bb 32
#define Hh 1024
#define Ss 512
#define Tt 32
#define N3 3072
#define NN 6144
#define NCTA 96          // 48 row-tiles x 2 K-splits
#define DSMEM 65536      // B block staging

// ===================== helpers =====================
__device__ __forceinline__ uint32_t pack_bf(__nv_bfloat16 x, __nv_bfloat16 y) {
    return (uint32_t)__bfloat16_as_ushort(x) | ((uint32_t)__bfloat16_as_ushort(y) << 16);
}
__device__ __forceinline__ void bsplit(float v, __nv_bfloat16& hi, __nv_bfloat16& lo) {
    hi = __float2bfloat16(v);
    lo = __float2bfloat16(v - __bfloat162float(hi));
}
__device__ __forceinline__ float fsigmoid(float x) {
    return 1.f / (1.f + __expf(-x));           // x=-inf -> 0, +inf -> 1 (no NaN)
}
__device__ __forceinline__ float ftanh(float x) {
    return 2.f / (1.f + __expf(-2.f * x)) - 1.f; // -inf -> -1, +inf -> 1 (no NaN)
}
// mma.sync m16n8k16 row.col bf16 -> f32
__device__ __forceinline__ void mma16816(float* c, const uint32_t* a, uint32_t b0, uint32_t b1) {
    asm volatile(
        "mma.sync.aligned.m16n8k16.row.col.f32.bf16.bf16.f32 "
        "{%0,%1,%2,%3}, {%4,%5,%6,%7}, {%8,%9}, {%0,%1,%2,%3};"
        : "+f"(c[0]), "+f"(c[1]), "+f"(c[2]), "+f"(c[3])
        : "r"(a[0]), "r"(a[1]), "r"(a[2]), "r"(a[3]), "r"(b0), "r"(b1));
}
// B-fragment byte offset (within one 32KB prec block) for element (k=j%512, n=b)
__device__ __forceinline__ uint32_t bfr_off(int j, int b, int& kz) {
    kz = j >> 9;
    int kk = j & 511;
    int kc = kk >> 4, r = kk & 15;
    int nn = b >> 3, g = b & 7, t = (r & 7) >> 1;
    return (uint32_t)(kc * 1024 + nn * 256 + (g * 4 + t) * 8 + ((r >= 8) ? 4 : 0) + (r & 1) * 2);
}

// ===================== device scratch =====================
__device__ __align__(128) uint4 g_wfrh[786432];   // A frags hi: [nt 48][kz 2][w 8][kc 32][lane 32]
__device__ __align__(128) uint4 g_wfrl[786432];   // A frags lo
__device__ __align__(128) char g_bfr[262144];     // B frags: [side 2][kz 2][prec 2][...]
__device__ __align__(16) float g_yT[(size_t)2 * Bb * NN]; // y: [kz][batch][gate]
__device__ __align__(16) float g_a[Bb * Ss];
__device__ __align__(16) float g_v1[Hh];
__device__ __align__(16) float g_v2[Hh];
__device__ __align__(16) float g_bias[NN];
// flag-based sync (no atomics)
__device__ volatile unsigned g_gemm_flag[NCTA];
__device__ volatile unsigned g_h_flag[Bb];
__device__ volatile unsigned g_x_flag[Bb];

// ===================== sync helpers =====================
__device__ __forceinline__ void wait_ge(volatile unsigned* f, int n, unsigned tgt) {
    bool ok;
    do {
        unsigned v = (threadIdx.x < (unsigned)n) ? f[threadIdx.x] : tgt;
        ok = __syncthreads_and(v >= tgt);
    } while (!ok);
    __threadfence();
}
__device__ __forceinline__ void arrive(volatile unsigned* slot, unsigned val) {
    __threadfence();
    __syncthreads();
    if (threadIdx.x == 0) *slot = val;
}

// ===================== prep kernels =====================
__global__ void prep_wfr(const float* __restrict__ w_ih, const float* __restrict__ w_hh) {
    int idx = blockIdx.x * 256 + threadIdx.x;
    int lane = idx & 31;
    int kc = (idx >> 5) & 31;
    int w = (idx >> 10) & 7;
    int kz = (idx >> 13) & 1;
    int nt = idx >> 14;
    int g = lane >> 2, t = lane & 3;
    int r0 = nt * 128 + w * 16 + g;
    int r1 = r0 + 8;
    int k0 = kz * 512 + kc * 16 + 2 * t;

    float v[8];
    int rows[2] = {r0, r1};
#pragma unroll
    for (int rr = 0; rr < 2; rr++) {
        const float* W = (rows[rr] < N3) ? (w_ih + (size_t)rows[rr] * Hh)
                                         : (w_hh + (size_t)(rows[rr] - N3) * Hh);
        v[rr * 2 + 0] = W[k0];
        v[rr * 2 + 1] = W[k0 + 1];
        v[rr * 2 + 4] = W[k0 + 8];
        v[rr * 2 + 5] = W[k0 + 9];
    }
    uint32_t hi[4], lo[4];
#pragma unroll
    for (int i = 0; i < 4; i++) {
        __nv_bfloat16 h0, l0, h1, l1;
        bsplit(v[2 * i], h0, l0);
        bsplit(v[2 * i + 1], h1, l1);
        hi[i] = pack_bf(h0, h1);
        lo[i] = pack_bf(l0, l1);
    }
    g_wfrh[idx] = make_uint4(hi[0], hi[1], hi[2], hi[3]);
    g_wfrl[idx] = make_uint4(lo[0], lo[1], lo[2], lo[3]);
}

// initial B pack: x = features (hi/lo), h = 0; reset flags
__global__ void prep_pack_b(const float* __restrict__ features) {
    int b = blockIdx.x, tid = threadIdx.x;
    if (b == 0) {
        if (tid < NCTA) g_gemm_flag[tid] = 0u;
        if (tid < Bb) { g_h_flag[tid] = 0u; g_x_flag[tid] = 0u; }
    }
#pragma unroll
    for (int jj = 0; jj < 4; jj++) {
        int j = tid + jj * 256;
        float v = features[b * Hh + j];
        __nv_bfloat16 hi, lo;
        bsplit(v, hi, lo);
        int kz;
        uint32_t off = bfr_off(j, b, kz);
        char* px = g_bfr + kz * 65536;
        *(unsigned short*)(px + off) = __bfloat16_as_ushort(hi);
        *(unsigned short*)(px + 32768 + off) = __bfloat16_as_ushort(lo);
        char* ph = g_bfr + 131072 + kz * 65536;
        *(unsigned short*)(ph + off) = 0;
        *(unsigned short*)(ph + 32768 + off) = 0;
    }
}

__global__ void prep_v(const float* __restrict__ W1, const float* __restrict__ W2,
                       const float* __restrict__ V) {
    __shared__ float vs[Hh];
    int tid = threadIdx.x;
    for (int i = tid; i < Hh; i += 256) vs[i] = V[i];
    __syncthreads();
    int sel = blockIdx.x >> 2;
    int d = (blockIdx.x & 3) * 256 + tid;
    const float* W = sel ? W2 : W1;
    float acc = 0.f;
    for (int h = 0; h < Hh; h++) acc = fmaf(vs[h], W[(size_t)h * Hh + d], acc);
    if (sel) g_v2[d] = acc; else g_v1[d] = acc;
}

__global__ void prep_bias(const float* __restrict__ b_ih, const float* __restrict__ b_hh) {
    int i = blockIdx.x * 1024 + threadIdx.x;
    g_bias[i] = (i < N3) ? b_ih[i] : b_hh[i - N3];
}

__global__ void prep_a(const float* __restrict__ inputs) {
    __shared__ float v2s[Hh];
    int tid = threadIdx.x;
    for (int i = tid; i < Hh; i += 256) v2s[i] = g_v2[i];
    __syncthreads();
    int warp = tid >> 5, lane = tid & 31;
    int row = blockIdx.x * 8 + warp;
    const float* r = inputs + (size_t)row * Hh;
    float acc = 0.f;
#pragma unroll
    for (int i = 0; i < 8; i++) {
        float4 x4 = *(const float4*)&r[(i * 32 + lane) * 4];
        float4 v4 = *(const float4*)&v2s[(i * 32 + lane) * 4];
        acc += x4.x * v4.x + x4.y * v4.y + x4.z * v4.z + x4.w * v4.w;
    }
#pragma unroll
    for (int o = 16; o > 0; o >>= 1) acc += __shfl_xor_sync(0xFFFFFFFFu, acc, o);
    if (lane == 0) g_a[row] = acc;
}

// ===================== persistent GRU loop =====================
extern __shared__ char dsm[];

__global__ void __launch_bounds__(256, 1)
gru_persist(const float* __restrict__ inputs, const float* __restrict__ mask,
            float* __restrict__ probs) {
    const int c = blockIdx.x;           // 0..95
    const int nt = c >> 1;              // row tile 0..47
    const int kz = c & 1;               // K-split half
    const int tid = threadIdx.x;
    const int wid = tid >> 5;
    const int lane = tid & 31;
    const int side = (nt >= 24) ? 1 : 0; // 0: x-side rows, 1: h-side rows
    const int b = c;                     // epilogue batch (c < 32 only)
    const bool is_epi = (c < Bb);

    const uint4* Ah = g_wfrh + (((size_t)nt * 2 + kz) * 8 + wid) * 1024;
    const uint4* Al = g_wfrl + (((size_t)nt * 2 + kz) * 8 + wid) * 1024;
    const char* bsrc = g_bfr + side * 131072 + kz * 65536;

    float* red = (float*)dsm;      // reused after GEMM consumes smem
    float* sv = (float*)(dsm + 64);
    int* si = (int*)(dsm + 128);

    // ---- hoist epilogue constants into registers ----
    float hreg[4];                 // persistent hidden state for batch b
    float brr[4], bzz[4], bni[4], bnh[4], v1r[4];
    float areg0 = 0.f, areg1 = 0.f, mk0 = 0.f, mk1 = 0.f;
    if (is_epi) {
#pragma unroll
        for (int k = 0; k < 4; k++) {
            int j = tid + 256 * k;
            hreg[k] = 0.f;
            brr[k] = g_bias[j] + g_bias[3072 + j];
            bzz[k] = g_bias[1024 + j] + g_bias[4096 + j];
            bni[k] = g_bias[2048 + j];
            bnh[k] = g_bias[5120 + j];
            v1r[k] = g_v1[j];
        }
        areg0 = g_a[b * Ss + tid];
        areg1 = g_a[b * Ss + tid + 256];
        mk0 = mask[b * Ss + tid];
        mk1 = mask[b * Ss + tid + 256];
    }

    for (int t = 0; t < Tt; t++) {
        // ---- wait for this side's B operand to be ready ----
        if (side == 0) wait_ge(g_x_flag, Bb, (unsigned)t);
        else           wait_ge(g_h_flag, Bb, (unsigned)t);

        // ---- stage B block (64KB) into smem ----
        {
            const uint4* s = (const uint4*)bsrc;
            uint4* d = (uint4*)dsm;
#pragma unroll 4
            for (int i = tid; i < 4096; i += 256) d[i] = s[i];
        }
        __syncthreads();

        // ---- GEMM: 128 rows x 32 batch x K=512, 3-term bf16 split ----
        float acc[4][4];
#pragma unroll
        for (int i = 0; i < 4; i++)
#pragma unroll
            for (int j = 0; j < 4; j++) acc[i][j] = 0.f;

        uint4 ah = Ah[lane];
        uint4 al = Al[lane];
#pragma unroll 2
        for (int kc = 0; kc < 32; kc++) {
            uint4 ah2, al2;
            if (kc < 31) { ah2 = Ah[(kc + 1) * 32 + lane]; al2 = Al[(kc + 1) * 32 + lane]; }
            const char* bb = dsm + kc * 1024 + lane * 8;
#pragma unroll
            for (int nn = 0; nn < 4; nn++) {
                uint2 bh = *(const uint2*)(bb + nn * 256);
                uint2 bl = *(const uint2*)(bb + 32768 + nn * 256);
                mma16816(acc[nn], &ah.x, bh.x, bh.y);
                mma16816(acc[nn], &ah.x, bl.x, bl.y);
                mma16816(acc[nn], &al.x, bh.x, bh.y);
            }
            ah = ah2; al = al2;
        }

        // ---- store y transposed: g_yT[kz][batch][gate] ----
        {
            float* y0 = g_yT + (size_t)kz * Bb * NN;
            int r0 = nt * 128 + wid * 16 + (lane >> 2);
            int c0 = 2 * (lane & 3);
#pragma unroll
            for (int nn = 0; nn < 4; nn++) {
                int col = nn * 8 + c0;
                y0[(size_t)col * NN + r0] = acc[nn][0];
                y0[(size_t)(col + 1) * NN + r0] = acc[nn][1];
                y0[(size_t)col * NN + r0 + 8] = acc[nn][2];
                y0[(size_t)(col + 1) * NN + r0 + 8] = acc[nn][3];
            }
        }
        arrive(&g_gemm_flag[c], (unsigned)(t + 1));

        // ---- epilogue on CTAs 0..31 (batch b) ----
        if (is_epi) {
            wait_ge((volatile unsigned*)g_gemm_flag, NCTA, (unsigned)(t + 1));

            const float* y0 = g_yT + (size_t)b * NN;
            const float* y1 = g_yT + (size_t)(Bb + b) * NN;
            float cpart = 0.f;
            // ---- part A: gates, h update, h repack ----
#pragma unroll
            for (int k = 0; k < 4; k++) {
                int j = tid + 256 * k;
                float gir = y0[j] + y1[j];
                float giz = y0[1024 + j] + y1[1024 + j];
                float gin = y0[2048 + j] + y1[2048 + j];
                float ghr = y0[3072 + j] + y1[3072 + j];
                float ghz = y0[4096 + j] + y1[4096 + j];
                float ghn = y0[5120 + j] + y1[5120 + j];
                float r = fsigmoid(gir + ghr + brr[k]);
                float z = fsigmoid(giz + ghz + bzz[k]);
                float nv = ftanh(gin + bni[k] + r * (ghn + bnh[k]));
                float hnew = (1.f - z) * nv + z * hreg[k];
                hreg[k] = hnew;
                __nv_bfloat16 hi, lo;
                bsplit(hnew, hi, lo);
                int kz2;
                uint32_t off = bfr_off(j, b, kz2);
                char* ph = g_bfr + 131072 + kz2 * 65536;
                *(unsigned short*)(ph + off) = __bfloat16_as_ushort(hi);
                *(unsigned short*)(ph + 32768 + off) = __bfloat16_as_ushort(lo);
                cpart = fmaf(v1r[k], hnew, cpart);
            }
            // release h: h-side GEMM CTAs can start next step NOW
            arrive(&g_h_flag[b], (unsigned)(t + 1));

            // ---- part B: c reduce, scores, argmax, x gather/repack ----
#pragma unroll
            for (int o = 16; o > 0; o >>= 1) cpart += __shfl_xor_sync(0xFFFFFFFFu, cpart, o);
            if (lane == 0) red[wid] = cpart;
            __syncthreads();
            if (wid == 0) {
                float v = (lane < 8) ? red[lane] : 0.f;
#pragma unroll
                for (int o = 4; o > 0; o >>= 1) v += __shfl_xor_sync(0xFFFFFFFFu, v, o);
                if (lane == 0) red[0] = v;
            }
            __syncthreads();
            float c0 = red[0];

            float s0 = ftanh(c0 + areg0);
            float s1 = ftanh(c0 + areg1);
            float* pr = probs + ((size_t)b * Tt + t) * Ss;
            pr[tid] = s0;
            pr[tid + 256] = s1;
            float m0 = s0 + mk0;
            float m1 = s1 + mk1;
            float bv = m0;
            int bi = tid;
            if (m1 > bv) { bv = m1; bi = tid + 256; }
#pragma unroll
            for (int o = 16; o > 0; o >>= 1) {
                float v = __shfl_xor_sync(0xFFFFFFFFu, bv, o);
                int ii = __shfl_xor_sync(0xFFFFFFFFu, bi, o);
                if (v > bv || (v == bv && ii < bi)) { bv = v; bi = ii; }
            }
            if (lane == 0) { sv[wid] = bv; si[wid] = bi; }
            __syncthreads();
            if (wid == 0) {
                float v = (lane < 8) ? sv[lane] : -3.4e38f;
                int ii = (lane < 8) ? si[lane] : (1 << 30);
#pragma unroll
                for (int o = 4; o > 0; o >>= 1) {
                    float v2 = __shfl_xor_sync(0xFFFFFFFFu, v, o);
                    int i2 = __shfl_xor_sync(0xFFFFFFFFu, ii, o);
                    if (v2 > v || (v2 == v && i2 < ii)) { v = v2; ii = i2; }
                }
                if (lane == 0) si[0] = ii;
            }
            __syncthreads();
            int idx = si[0];
            const float* xr = inputs + ((size_t)b * Ss + idx) * Hh;
#pragma unroll
            for (int k = 0; k < 4; k++) {
                int j = tid + 256 * k;
                float xv = xr[j];
                __nv_bfloat16 hi, lo;
                bsplit(xv, hi, lo);
                int kz2;
                uint32_t off = bfr_off(j, b, kz2);
                char* px = g_bfr + kz2 * 65536;
                *(unsigned short*)(px + off) = __bfloat16_as_ushort(hi);
                *(unsigned short*)(px + 32768 + off) = __bfloat16_as_ushort(lo);
            }
            arrive(&g_x_flag[b], (unsigned)(t + 1));
        }
    }
}

// ===================== context (step-0 softmax) =====================
__global__ void __launch_bounds__(256) ctx_kernel(const float* __restrict__ inputs,
                                                  const float* __restrict__ mask,
                                                  const float* __restrict__ probs,
                                                  float* __restrict__ ctx) {
    const int b = blockIdx.x;
    const int hq = blockIdx.y;
    const int tid = threadIdx.x;
    __shared__ float p[Ss];
    __shared__ float red[256];

    for (int s = tid; s < Ss; s += 256)
        p[s] = probs[(size_t)b * Tt * Ss + s] + mask[b * Ss + s];
    __syncthreads();
    float m = -1e30f;
    for (int s = tid; s < Ss; s += 256) m = fmaxf(m, p[s]);
    red[tid] = m;
    __syncthreads();
    for (int st = 128; st >= 1; st >>= 1) {
        if (tid < st) red[tid] = fmaxf(red[tid], red[tid + st]);
        __syncthreads();
    }
    const float mx = red[0];
    __syncthreads();
    float sm = 0.f;
    for (int s = tid; s < Ss; s += 256) {
        float e = expf(p[s] - mx);
        p[s] = e;
        sm += e;
    }
    red[tid] = sm;
    __syncthreads();
    for (int st = 128; st >= 1; st >>= 1) {
        if (tid < st) red[tid] += red[tid + st];
        __syncthreads();
    }
    const float Z = red[0];
    __syncthreads();
    const int h = hq * 256 + tid;
    float acc = 0.f;
    for (int s = 0; s < Ss; s++)
        acc = fmaf(p[s], inputs[((size_t)b * Ss + s) * Hh + h], acc);
    ctx[b * Hh + h] = acc / Z;
}

// ===================== launch =====================
extern "C" void kernel_launch(void* const* d_in, const int* in_sizes, int n_in,
                              void* d_out, int out_size) {
    const float* inputs   = (const float*)d_in[0];
    const float* mask     = (const float*)d_in[1];
    // d_in[2] = inputs_embeds (unused, use_emb=False)
    const float* features = (const float*)d_in[3];
    const float* w_ih     = (const float*)d_in[4];
    const float* b_ih     = (const float*)d_in[5];
    const float* w_hh     = (const float*)d_in[6];
    const float* b_hh     = (const float*)d_in[7];
    const float* W1       = (const float*)d_in[8];
    const float* W2       = (const float*)d_in[9];
    const float* V        = (const float*)d_in[10];

    float* out   = (float*)d_out;
    float* probs = out;                            // [B, T, S]
    float* ctx   = out + (size_t)Bb * Tt * Ss;     // [B, H]

    cudaFuncSetAttribute(gru_persist, cudaFuncAttributeMaxDynamicSharedMemorySize, DSMEM);

    prep_pack_b<<<Bb, 256>>>(features);
    prep_v<<<8, 256>>>(W1, W2, V);
    prep_wfr<<<3072, 256>>>(w_ih, w_hh);
    prep_bias<<<NN / 1024, 1024>>>(b_ih, b_hh);
    prep_a<<<(Bb * Ss) / 8, 256>>>(inputs);

    gru_persist<<<NCTA, 256, DSMEM>>>(inputs, mask, probs);

    ctx_kernel<<<dim3(Bb, 4), 256>>>(inputs, mask, probs, ctx);
}

// round 6
// speedup vs baseline: 1.2640x; 1.2640x over previous
#include <cuda_runtime.h>
#include <cuda_bf16.h>
#include <cstdint>
#include <math.h>

#define Bb 32
#define Hh 1024
#define Ss 512
#define Tt 32
#define N3 3072
#define NN 6144
#define NCTA 96          // 48 row-tiles x 2 K-splits
#define DSMEM 65536      // B block staging

// ===================== helpers =====================
__device__ __forceinline__ uint32_t pack_bf(__nv_bfloat16 x, __nv_bfloat16 y) {
    return (uint32_t)__bfloat16_as_ushort(x) | ((uint32_t)__bfloat16_as_ushort(y) << 16);
}
__device__ __forceinline__ void bsplit(float v, __nv_bfloat16& hi, __nv_bfloat16& lo) {
    hi = __float2bfloat16(v);
    lo = __float2bfloat16(v - __bfloat162float(hi));
}
__device__ __forceinline__ float fsigmoid(float x) {
    return 1.f / (1.f + __expf(-x));
}
__device__ __forceinline__ float ftanh(float x) {
    return 2.f / (1.f + __expf(-2.f * x)) - 1.f;
}
// mma.sync m16n8k16 row.col bf16 -> f32
__device__ __forceinline__ void mma16816(float* c, const uint32_t* a, uint32_t b0, uint32_t b1) {
    asm volatile(
        "mma.sync.aligned.m16n8k16.row.col.f32.bf16.bf16.f32 "
        "{%0,%1,%2,%3}, {%4,%5,%6,%7}, {%8,%9}, {%0,%1,%2,%3};"
        : "+f"(c[0]), "+f"(c[1]), "+f"(c[2]), "+f"(c[3])
        : "r"(a[0]), "r"(a[1]), "r"(a[2]), "r"(a[3]), "r"(b0), "r"(b1));
}
// B-fragment byte offset (within one 32KB prec block) for element (k=j%512, n=b)
__device__ __forceinline__ uint32_t bfr_off(int j, int b, int& kz) {
    kz = j >> 9;
    int kk = j & 511;
    int kc = kk >> 4, r = kk & 15;
    int nn = b >> 3, g = b & 7, t = (r & 7) >> 1;
    return (uint32_t)(kc * 1024 + nn * 256 + (g * 4 + t) * 8 + ((r >= 8) ? 4 : 0) + (r & 1) * 2);
}

// ===================== device scratch =====================
__device__ __align__(128) uint4 g_wfrh[786432];   // A frags hi: [nt 48][kz 2][w 8][kc 32][lane 32]
__device__ __align__(128) uint4 g_wfrl[786432];   // A frags lo
__device__ __align__(128) char g_bfr[262144];     // B frags: [side 2][kz 2][prec 2][...]
__device__ __align__(16) float g_yT[(size_t)2 * Bb * NN]; // y: [kz][batch][gate]
__device__ __align__(16) float g_a[Bb * Ss];
__device__ __align__(16) float g_v1[Hh];
__device__ __align__(16) float g_v2[Hh];
__device__ __align__(16) float g_bias[NN];
// central barrier: atomic arrivals + store/load release (NO polling RMWs)
__device__ unsigned g_arrive;
__device__ volatile unsigned g_release;

__device__ __forceinline__ void gbar(unsigned idx) {
    __syncthreads();
    if (threadIdx.x == 0) {
        __threadfence();
        unsigned prev = atomicAdd(&g_arrive, 1u);
        if (prev == idx * NCTA - 1u) {
            __threadfence();
            g_release = idx;               // single release store
        } else {
            while (g_release < idx) { }    // plain volatile loads
        }
        __threadfence();
    }
    __syncthreads();
}

// ===================== prep kernels =====================
__global__ void prep_wfr(const float* __restrict__ w_ih, const float* __restrict__ w_hh) {
    int idx = blockIdx.x * 256 + threadIdx.x;
    int lane = idx & 31;
    int kc = (idx >> 5) & 31;
    int w = (idx >> 10) & 7;
    int kz = (idx >> 13) & 1;
    int nt = idx >> 14;
    int g = lane >> 2, t = lane & 3;
    int r0 = nt * 128 + w * 16 + g;
    int r1 = r0 + 8;
    int k0 = kz * 512 + kc * 16 + 2 * t;

    float v[8];
    int rows[2] = {r0, r1};
#pragma unroll
    for (int rr = 0; rr < 2; rr++) {
        const float* W = (rows[rr] < N3) ? (w_ih + (size_t)rows[rr] * Hh)
                                         : (w_hh + (size_t)(rows[rr] - N3) * Hh);
        v[rr * 2 + 0] = W[k0];
        v[rr * 2 + 1] = W[k0 + 1];
        v[rr * 2 + 4] = W[k0 + 8];
        v[rr * 2 + 5] = W[k0 + 9];
    }
    uint32_t hi[4], lo[4];
#pragma unroll
    for (int i = 0; i < 4; i++) {
        __nv_bfloat16 h0, l0, h1, l1;
        bsplit(v[2 * i], h0, l0);
        bsplit(v[2 * i + 1], h1, l1);
        hi[i] = pack_bf(h0, h1);
        lo[i] = pack_bf(l0, l1);
    }
    g_wfrh[idx] = make_uint4(hi[0], hi[1], hi[2], hi[3]);
    g_wfrl[idx] = make_uint4(lo[0], lo[1], lo[2], lo[3]);
}

// initial B pack: x = features (hi/lo), h = 0; reset barrier state
__global__ void prep_pack_b(const float* __restrict__ features) {
    int b = blockIdx.x, tid = threadIdx.x;
    if (b == 0 && tid == 0) { g_arrive = 0u; g_release = 0u; }
#pragma unroll
    for (int jj = 0; jj < 4; jj++) {
        int j = tid + jj * 256;
        float v = features[b * Hh + j];
        __nv_bfloat16 hi, lo;
        bsplit(v, hi, lo);
        int kz;
        uint32_t off = bfr_off(j, b, kz);
        char* px = g_bfr + kz * 65536;
        *(unsigned short*)(px + off) = __bfloat16_as_ushort(hi);
        *(unsigned short*)(px + 32768 + off) = __bfloat16_as_ushort(lo);
        char* ph = g_bfr + 131072 + kz * 65536;
        *(unsigned short*)(ph + off) = 0;
        *(unsigned short*)(ph + 32768 + off) = 0;
    }
}

__global__ void prep_v(const float* __restrict__ W1, const float* __restrict__ W2,
                       const float* __restrict__ V) {
    __shared__ float vs[Hh];
    int tid = threadIdx.x;
    for (int i = tid; i < Hh; i += 256) vs[i] = V[i];
    __syncthreads();
    int sel = blockIdx.x >> 2;
    int d = (blockIdx.x & 3) * 256 + tid;
    const float* W = sel ? W2 : W1;
    float acc = 0.f;
    for (int h = 0; h < Hh; h++) acc = fmaf(vs[h], W[(size_t)h * Hh + d], acc);
    if (sel) g_v2[d] = acc; else g_v1[d] = acc;
}

__global__ void prep_bias(const float* __restrict__ b_ih, const float* __restrict__ b_hh) {
    int i = blockIdx.x * 1024 + threadIdx.x;
    g_bias[i] = (i < N3) ? b_ih[i] : b_hh[i - N3];
}

__global__ void prep_a(const float* __restrict__ inputs) {
    __shared__ float v2s[Hh];
    int tid = threadIdx.x;
    for (int i = tid; i < Hh; i += 256) v2s[i] = g_v2[i];
    __syncthreads();
    int warp = tid >> 5, lane = tid & 31;
    int row = blockIdx.x * 8 + warp;
    const float* r = inputs + (size_t)row * Hh;
    float acc = 0.f;
#pragma unroll
    for (int i = 0; i < 8; i++) {
        float4 x4 = *(const float4*)&r[(i * 32 + lane) * 4];
        float4 v4 = *(const float4*)&v2s[(i * 32 + lane) * 4];
        acc += x4.x * v4.x + x4.y * v4.y + x4.z * v4.z + x4.w * v4.w;
    }
#pragma unroll
    for (int o = 16; o > 0; o >>= 1) acc += __shfl_xor_sync(0xFFFFFFFFu, acc, o);
    if (lane == 0) g_a[row] = acc;
}

// ===================== persistent GRU loop =====================
extern __shared__ char dsm[];

__global__ void __launch_bounds__(256, 1)
gru_persist(const float* __restrict__ inputs, const float* __restrict__ mask,
            float* __restrict__ probs) {
    const int c = blockIdx.x;           // 0..95
    const int nt = c >> 1;              // row tile 0..47
    const int kz = c & 1;               // K-split half
    const int tid = threadIdx.x;
    const int wid = tid >> 5;
    const int lane = tid & 31;
    const int side = (nt >= 24) ? 1 : 0; // 0: x-side rows, 1: h-side rows
    const int b = c;                     // epilogue batch (c < 32 only)
    const bool is_epi = (c < Bb);

    const uint4* Ah = g_wfrh + (((size_t)nt * 2 + kz) * 8 + wid) * 1024;
    const uint4* Al = g_wfrl + (((size_t)nt * 2 + kz) * 8 + wid) * 1024;
    const char* bsrc = g_bfr + side * 131072 + kz * 65536;

    float* red = (float*)dsm;      // smem reused after GEMM stage consumed
    float* sv = (float*)(dsm + 64);
    int* si = (int*)(dsm + 128);

    // ---- hoist epilogue constants into registers ----
    float hreg[4];
    float brr[4], bzz[4], bni[4], bnh[4], v1r[4];
    float areg0 = 0.f, areg1 = 0.f, mk0 = 0.f, mk1 = 0.f;
    if (is_epi) {
#pragma unroll
        for (int k = 0; k < 4; k++) {
            int j = tid + 256 * k;
            hreg[k] = 0.f;
            brr[k] = g_bias[j] + g_bias[3072 + j];
            bzz[k] = g_bias[1024 + j] + g_bias[4096 + j];
            bni[k] = g_bias[2048 + j];
            bnh[k] = g_bias[5120 + j];
            v1r[k] = g_v1[j];
        }
        areg0 = g_a[b * Ss + tid];
        areg1 = g_a[b * Ss + tid + 256];
        mk0 = mask[b * Ss + tid];
        mk1 = mask[b * Ss + tid + 256];
    }

    for (int t = 0; t < Tt; t++) {
        // ---- stage B block (64KB) into smem ----
        {
            const uint4* s = (const uint4*)bsrc;
            uint4* d = (uint4*)dsm;
#pragma unroll 4
            for (int i = tid; i < 4096; i += 256) d[i] = s[i];
        }
        __syncthreads();

        // ---- GEMM: 128 rows x 32 batch x K=512, 3-term bf16 split ----
        float acc[4][4];
#pragma unroll
        for (int i = 0; i < 4; i++)
#pragma unroll
            for (int j = 0; j < 4; j++) acc[i][j] = 0.f;

        uint4 ah = Ah[lane];
        uint4 al = Al[lane];
#pragma unroll 2
        for (int kc = 0; kc < 32; kc++) {
            uint4 ah2, al2;
            if (kc < 31) { ah2 = Ah[(kc + 1) * 32 + lane]; al2 = Al[(kc + 1) * 32 + lane]; }
            const char* bb = dsm + kc * 1024 + lane * 8;
#pragma unroll
            for (int nn = 0; nn < 4; nn++) {
                uint2 bh = *(const uint2*)(bb + nn * 256);
                uint2 bl = *(const uint2*)(bb + 32768 + nn * 256);
                mma16816(acc[nn], &ah.x, bh.x, bh.y);
                mma16816(acc[nn], &ah.x, bl.x, bl.y);
                mma16816(acc[nn], &al.x, bh.x, bh.y);
            }
            ah = ah2; al = al2;
        }

        // ---- store y transposed: g_yT[kz][batch][gate] ----
        {
            float* y0 = g_yT + (size_t)kz * Bb * NN;
            int r0 = nt * 128 + wid * 16 + (lane >> 2);
            int c0 = 2 * (lane & 3);
#pragma unroll
            for (int nn = 0; nn < 4; nn++) {
                int col = nn * 8 + c0;
                y0[(size_t)col * NN + r0] = acc[nn][0];
                y0[(size_t)(col + 1) * NN + r0] = acc[nn][1];
                y0[(size_t)col * NN + r0 + 8] = acc[nn][2];
                y0[(size_t)(col + 1) * NN + r0 + 8] = acc[nn][3];
            }
        }
        gbar((unsigned)(2 * t + 1));

        // ---- epilogue on CTAs 0..31 (batch b) ----
        if (is_epi) {
            const float* y0 = g_yT + (size_t)b * NN;
            const float* y1 = g_yT + (size_t)(Bb + b) * NN;
            float cpart = 0.f;
#pragma unroll
            for (int k = 0; k < 4; k++) {
                int j = tid + 256 * k;
                float gir = y0[j] + y1[j];
                float giz = y0[1024 + j] + y1[1024 + j];
                float gin = y0[2048 + j] + y1[2048 + j];
                float ghr = y0[3072 + j] + y1[3072 + j];
                float ghz = y0[4096 + j] + y1[4096 + j];
                float ghn = y0[5120 + j] + y1[5120 + j];
                float r = fsigmoid(gir + ghr + brr[k]);
                float z = fsigmoid(giz + ghz + bzz[k]);
                float nv = ftanh(gin + bni[k] + r * (ghn + bnh[k]));
                float hnew = (1.f - z) * nv + z * hreg[k];
                hreg[k] = hnew;
                __nv_bfloat16 hi, lo;
                bsplit(hnew, hi, lo);
                int kz2;
                uint32_t off = bfr_off(j, b, kz2);
                char* ph = g_bfr + 131072 + kz2 * 65536;
                *(unsigned short*)(ph + off) = __bfloat16_as_ushort(hi);
                *(unsigned short*)(ph + 32768 + off) = __bfloat16_as_ushort(lo);
                cpart = fmaf(v1r[k], hnew, cpart);
            }
            // ---- c reduce, scores, argmax, x gather/repack ----
#pragma unroll
            for (int o = 16; o > 0; o >>= 1) cpart += __shfl_xor_sync(0xFFFFFFFFu, cpart, o);
            if (lane == 0) red[wid] = cpart;
            __syncthreads();
            if (wid == 0) {
                float v = (lane < 8) ? red[lane] : 0.f;
#pragma unroll
                for (int o = 4; o > 0; o >>= 1) v += __shfl_xor_sync(0xFFFFFFFFu, v, o);
                if (lane == 0) red[0] = v;
            }
            __syncthreads();
            float c0 = red[0];

            float s0 = ftanh(c0 + areg0);
            float s1 = ftanh(c0 + areg1);
            float* pr = probs + ((size_t)b * Tt + t) * Ss;
            pr[tid] = s0;
            pr[tid + 256] = s1;
            float m0 = s0 + mk0;
            float m1 = s1 + mk1;
            float bv = m0;
            int bi = tid;
            if (m1 > bv) { bv = m1; bi = tid + 256; }
#pragma unroll
            for (int o = 16; o > 0; o >>= 1) {
                float v = __shfl_xor_sync(0xFFFFFFFFu, bv, o);
                int ii = __shfl_xor_sync(0xFFFFFFFFu, bi, o);
                if (v > bv || (v == bv && ii < bi)) { bv = v; bi = ii; }
            }
            if (lane == 0) { sv[wid] = bv; si[wid] = bi; }
            __syncthreads();
            if (wid == 0) {
                float v = (lane < 8) ? sv[lane] : -3.4e38f;
                int ii = (lane < 8) ? si[lane] : (1 << 30);
#pragma unroll
                for (int o = 4; o > 0; o >>= 1) {
                    float v2 = __shfl_xor_sync(0xFFFFFFFFu, v, o);
                    int i2 = __shfl_xor_sync(0xFFFFFFFFu, ii, o);
                    if (v2 > v || (v2 == v && i2 < ii)) { v = v2; ii = i2; }
                }
                if (lane == 0) si[0] = ii;
            }
            __syncthreads();
            int idx = si[0];
            const float* xr = inputs + ((size_t)b * Ss + idx) * Hh;
#pragma unroll
            for (int k = 0; k < 4; k++) {
                int j = tid + 256 * k;
                float xv = xr[j];
                __nv_bfloat16 hi, lo;
                bsplit(xv, hi, lo);
                int kz2;
                uint32_t off = bfr_off(j, b, kz2);
                char* px = g_bfr + kz2 * 65536;
                *(unsigned short*)(px + off) = __bfloat16_as_ushort(hi);
                *(unsigned short*)(px + 32768 + off) = __bfloat16_as_ushort(lo);
            }
        }
        gbar((unsigned)(2 * t + 2));
    }
}

// ===================== context (step-0 softmax) =====================
__global__ void __launch_bounds__(256) ctx_kernel(const float* __restrict__ inputs,
                                                  const float* __restrict__ mask,
                                                  const float* __restrict__ probs,
                                                  float* __restrict__ ctx) {
    const int b = blockIdx.x;
    const int hq = blockIdx.y;
    const int tid = threadIdx.x;
    __shared__ float p[Ss];
    __shared__ float red[256];

    for (int s = tid; s < Ss; s += 256)
        p[s] = probs[(size_t)b * Tt * Ss + s] + mask[b * Ss + s];
    __syncthreads();
    float m = -1e30f;
    for (int s = tid; s < Ss; s += 256) m = fmaxf(m, p[s]);
    red[tid] = m;
    __syncthreads();
    for (int st = 128; st >= 1; st >>= 1) {
        if (tid < st) red[tid] = fmaxf(red[tid], red[tid + st]);
        __syncthreads();
    }
    const float mx = red[0];
    __syncthreads();
    float sm = 0.f;
    for (int s = tid; s < Ss; s += 256) {
        float e = expf(p[s] - mx);
        p[s] = e;
        sm += e;
    }
    red[tid] = sm;
    __syncthreads();
    for (int st = 128; st >= 1; st >>= 1) {
        if (tid < st) red[tid] += red[tid + st];
        __syncthreads();
    }
    const float Z = red[0];
    __syncthreads();
    const int h = hq * 256 + tid;
    float acc = 0.f;
    for (int s = 0; s < Ss; s++)
        acc = fmaf(p[s], inputs[((size_t)b * Ss + s) * Hh + h], acc);
    ctx[b * Hh + h] = acc / Z;
}

// ===================== launch =====================
extern "C" void kernel_launch(void* const* d_in, const int* in_sizes, int n_in,
                              void* d_out, int out_size) {
    const float* inputs   = (const float*)d_in[0];
    const float* mask     = (const float*)d_in[1];
    // d_in[2] = inputs_embeds (unused, use_emb=False)
    const float* features = (const float*)d_in[3];
    const float* w_ih     = (const float*)d_in[4];
    const float* b_ih     = (const float*)d_in[5];
    const float* w_hh     = (const float*)d_in[6];
    const float* b_hh     = (const float*)d_in[7];
    const float* W1       = (const float*)d_in[8];
    const float* W2       = (const float*)d_in[9];
    const float* V        = (const float*)d_in[10];

    float* out   = (float*)d_out;
    float* probs = out;                            // [B, T, S]
    float* ctx   = out + (size_t)Bb * Tt * Ss;     // [B, H]

    cudaFuncSetAttribute(gru_persist, cudaFuncAttributeMaxDynamicSharedMemorySize, DSMEM);

    prep_pack_b<<<Bb, 256>>>(features);
    prep_v<<<8, 256>>>(W1, W2, V);
    prep_wfr<<<3072, 256>>>(w_ih, w_hh);
    prep_bias<<<NN / 1024, 1024>>>(b_ih, b_hh);
    prep_a<<<(Bb * Ss) / 8, 256>>>(inputs);

    gru_persist<<<NCTA, 256, DSMEM>>>(inputs, mask, probs);

    ctx_kernel<<<dim3(Bb, 4), 256>>>(inputs, mask, probs, ctx);
}

// round 7
// speedup vs baseline: 1.3521x; 1.0697x over previous
#include <cuda_runtime.h>
#include <cuda_bf16.h>
#include <cstdint>
#include <math.h>

#define Bb 32
#define Hh 1024
#define Ss 512
#define Tt 32
#define N3 3072
#define NN 6144
#define NCTA 96          // 48 row-tiles x 2 K-splits
#define DSMEM 65536      // B block staging

// ===================== helpers =====================
__device__ __forceinline__ uint32_t smem_u32(const void* p) {
    uint32_t a;
    asm("{ .reg .u64 t; cvta.to.shared.u64 t, %1; cvt.u32.u64 %0, t; }" : "=r"(a) : "l"(p));
    return a;
}
__device__ __forceinline__ uint32_t pack_bf(__nv_bfloat16 x, __nv_bfloat16 y) {
    return (uint32_t)__bfloat16_as_ushort(x) | ((uint32_t)__bfloat16_as_ushort(y) << 16);
}
__device__ __forceinline__ void bsplit(float v, __nv_bfloat16& hi, __nv_bfloat16& lo) {
    hi = __float2bfloat16(v);
    lo = __float2bfloat16(v - __bfloat162float(hi));
}
__device__ __forceinline__ float fsigmoid(float x) {
    return 1.f / (1.f + __expf(-x));
}
__device__ __forceinline__ float ftanh(float x) {
    return 2.f / (1.f + __expf(-2.f * x)) - 1.f;
}
// mma.sync m16n8k16 row.col bf16 -> f32
__device__ __forceinline__ void mma16816(float* c, const uint32_t* a, uint32_t b0, uint32_t b1) {
    asm volatile(
        "mma.sync.aligned.m16n8k16.row.col.f32.bf16.bf16.f32 "
        "{%0,%1,%2,%3}, {%4,%5,%6,%7}, {%8,%9}, {%0,%1,%2,%3};"
        : "+f"(c[0]), "+f"(c[1]), "+f"(c[2]), "+f"(c[3])
        : "r"(a[0]), "r"(a[1]), "r"(a[2]), "r"(a[3]), "r"(b0), "r"(b1));
}
// B-fragment byte offset (within one 32KB prec block) for element (k=j%512, n=b)
__device__ __forceinline__ uint32_t bfr_off(int j, int b, int& kz) {
    kz = j >> 9;
    int kk = j & 511;
    int kc = kk >> 4, r = kk & 15;
    int nn = b >> 3, g = b & 7, t = (r & 7) >> 1;
    return (uint32_t)(kc * 1024 + nn * 256 + (g * 4 + t) * 8 + ((r >= 8) ? 4 : 0) + (r & 1) * 2);
}

// ===================== device scratch =====================
__device__ __align__(128) uint4 g_wfrh[786432];   // A frags hi: [nt 48][kz 2][w 8][kc 32][lane 32]
__device__ __align__(128) uint4 g_wfrl[786432];   // A frags lo
__device__ __align__(128) char g_bfr[262144];     // B frags: [side 2][kz 2][prec 2][...]
__device__ __align__(16) float g_yT[(size_t)2 * Bb * NN]; // y: [kz][batch][gate]
__device__ __align__(16) float g_a[Bb * Ss];
__device__ __align__(16) float g_v1[Hh];
__device__ __align__(16) float g_v2[Hh];
__device__ __align__(16) float g_bias[NN];
// split barriers: atomic arrivals + store/load release (no polling RMWs)
__device__ unsigned g_ycnt, g_hcnt, g_xcnt;
__device__ volatile unsigned g_yrel, g_hrel, g_xrel;

// ===================== prep kernels =====================
__global__ void prep_wfr(const float* __restrict__ w_ih, const float* __restrict__ w_hh) {
    int idx = blockIdx.x * 256 + threadIdx.x;
    int lane = idx & 31;
    int kc = (idx >> 5) & 31;
    int w = (idx >> 10) & 7;
    int kz = (idx >> 13) & 1;
    int nt = idx >> 14;
    int g = lane >> 2, t = lane & 3;
    int r0 = nt * 128 + w * 16 + g;
    int r1 = r0 + 8;
    int k0 = kz * 512 + kc * 16 + 2 * t;

    float v[8];
    int rows[2] = {r0, r1};
#pragma unroll
    for (int rr = 0; rr < 2; rr++) {
        const float* W = (rows[rr] < N3) ? (w_ih + (size_t)rows[rr] * Hh)
                                         : (w_hh + (size_t)(rows[rr] - N3) * Hh);
        v[rr * 2 + 0] = W[k0];
        v[rr * 2 + 1] = W[k0 + 1];
        v[rr * 2 + 4] = W[k0 + 8];
        v[rr * 2 + 5] = W[k0 + 9];
    }
    uint32_t hi[4], lo[4];
#pragma unroll
    for (int i = 0; i < 4; i++) {
        __nv_bfloat16 h0, l0, h1, l1;
        bsplit(v[2 * i], h0, l0);
        bsplit(v[2 * i + 1], h1, l1);
        hi[i] = pack_bf(h0, h1);
        lo[i] = pack_bf(l0, l1);
    }
    g_wfrh[idx] = make_uint4(hi[0], hi[1], hi[2], hi[3]);
    g_wfrl[idx] = make_uint4(lo[0], lo[1], lo[2], lo[3]);
}

// initial B pack: x = features (hi/lo), h = 0; reset barrier state
__global__ void prep_pack_b(const float* __restrict__ features) {
    int b = blockIdx.x, tid = threadIdx.x;
    if (b == 0 && tid == 0) {
        g_ycnt = 0u; g_hcnt = 0u; g_xcnt = 0u;
        g_yrel = 0u; g_hrel = 0u; g_xrel = 0u;
    }
#pragma unroll
    for (int jj = 0; jj < 4; jj++) {
        int j = tid + jj * 256;
        float v = features[b * Hh + j];
        __nv_bfloat16 hi, lo;
        bsplit(v, hi, lo);
        int kz;
        uint32_t off = bfr_off(j, b, kz);
        char* px = g_bfr + kz * 65536;
        *(unsigned short*)(px + off) = __bfloat16_as_ushort(hi);
        *(unsigned short*)(px + 32768 + off) = __bfloat16_as_ushort(lo);
        char* ph = g_bfr + 131072 + kz * 65536;
        *(unsigned short*)(ph + off) = 0;
        *(unsigned short*)(ph + 32768 + off) = 0;
    }
}

__global__ void prep_v(const float* __restrict__ W1, const float* __restrict__ W2,
                       const float* __restrict__ V) {
    __shared__ float vs[Hh];
    int tid = threadIdx.x;
    for (int i = tid; i < Hh; i += 256) vs[i] = V[i];
    __syncthreads();
    int sel = blockIdx.x >> 2;
    int d = (blockIdx.x & 3) * 256 + tid;
    const float* W = sel ? W2 : W1;
    float acc = 0.f;
    for (int h = 0; h < Hh; h++) acc = fmaf(vs[h], W[(size_t)h * Hh + d], acc);
    if (sel) g_v2[d] = acc; else g_v1[d] = acc;
}

__global__ void prep_bias(const float* __restrict__ b_ih, const float* __restrict__ b_hh) {
    int i = blockIdx.x * 1024 + threadIdx.x;
    g_bias[i] = (i < N3) ? b_ih[i] : b_hh[i - N3];
}

__global__ void prep_a(const float* __restrict__ inputs) {
    __shared__ float v2s[Hh];
    int tid = threadIdx.x;
    for (int i = tid; i < Hh; i += 256) v2s[i] = g_v2[i];
    __syncthreads();
    int warp = tid >> 5, lane = tid & 31;
    int row = blockIdx.x * 8 + warp;
    const float* r = inputs + (size_t)row * Hh;
    float acc = 0.f;
#pragma unroll
    for (int i = 0; i < 8; i++) {
        float4 x4 = *(const float4*)&r[(i * 32 + lane) * 4];
        float4 v4 = *(const float4*)&v2s[(i * 32 + lane) * 4];
        acc += x4.x * v4.x + x4.y * v4.y + x4.z * v4.z + x4.w * v4.w;
    }
#pragma unroll
    for (int o = 16; o > 0; o >>= 1) acc += __shfl_xor_sync(0xFFFFFFFFu, acc, o);
    if (lane == 0) g_a[row] = acc;
}

// ===================== persistent GRU loop =====================
extern __shared__ char dsm[];

__global__ void __launch_bounds__(256, 1)
gru_persist(const float* __restrict__ inputs, const float* __restrict__ mask,
            float* __restrict__ probs) {
    const int c = blockIdx.x;           // 0..95
    const int nt = c >> 1;              // row tile 0..47
    const int kz = c & 1;               // K-split half
    const int tid = threadIdx.x;
    const int wid = tid >> 5;
    const int lane = tid & 31;
    const int side = (nt >= 24) ? 1 : 0; // 0: x-side rows, 1: h-side rows
    const int b = c;                     // epilogue batch (c < 32 only)
    const bool is_epi = (c < Bb);

    const uint4* Ah = g_wfrh + (((size_t)nt * 2 + kz) * 8 + wid) * 1024;
    const uint4* Al = g_wfrl + (((size_t)nt * 2 + kz) * 8 + wid) * 1024;
    const char* bsrc = g_bfr + side * 131072 + kz * 65536;
    const uint32_t sb = smem_u32(dsm);

    float* red = (float*)dsm;
    float* sv = (float*)(dsm + 64);
    int* si = (int*)(dsm + 128);

    // ---- hoist epilogue constants ----
    float hreg[4];
    float brr[4], bzz[4], bni[4], bnh[4], v1r[4];
    float areg0 = 0.f, areg1 = 0.f, mk0 = 0.f, mk1 = 0.f;
    if (is_epi) {
#pragma unroll
        for (int k = 0; k < 4; k++) {
            int j = tid + 256 * k;
            hreg[k] = 0.f;
            brr[k] = g_bias[j] + g_bias[3072 + j];
            bzz[k] = g_bias[1024 + j] + g_bias[4096 + j];
            bni[k] = g_bias[2048 + j];
            bnh[k] = g_bias[5120 + j];
            v1r[k] = g_v1[j];
        }
        areg0 = g_a[b * Ss + tid];
        areg1 = g_a[b * Ss + tid + 256];
        mk0 = mask[b * Ss + tid];
        mk1 = mask[b * Ss + tid + 256];
    }

    for (int t = 0; t < Tt; t++) {
        // ---- wait for this side's operand (released by previous step's epilogue) ----
        if (tid == 0) {
            volatile unsigned* rel = side ? &g_hrel : &g_xrel;
            while (*rel < (unsigned)t) { }
            __threadfence();
        }
        __syncthreads();

        // ---- stage B block (64KB) into smem via cp.async ----
#pragma unroll
        for (int i = 0; i < 16; i++) {
            int idx = tid + i * 256;
            asm volatile("cp.async.cg.shared.global [%0], [%1], 16;"
                :: "r"(sb + idx * 16),
                   "l"(__cvta_generic_to_global(bsrc + idx * 16)) : "memory");
        }
        asm volatile("cp.async.commit_group;" ::: "memory");
        asm volatile("cp.async.wait_group 0;" ::: "memory");
        __syncthreads();

        // ---- GEMM: 128 rows x 32 batch x K=512, 3-term bf16 split ----
        float acc[4][4];
#pragma unroll
        for (int i = 0; i < 4; i++)
#pragma unroll
            for (int j = 0; j < 4; j++) acc[i][j] = 0.f;

        uint4 AH[4][2], AL[4][2];   // rotating pair buffers (prefetch depth 2 pairs)
#pragma unroll
        for (int p = 0; p < 2; p++) {
            AH[p][0] = Ah[(2 * p) * 32 + lane];
            AH[p][1] = Ah[(2 * p + 1) * 32 + lane];
            AL[p][0] = Al[(2 * p) * 32 + lane];
            AL[p][1] = Al[(2 * p + 1) * 32 + lane];
        }
#pragma unroll
        for (int p = 0; p < 16; p++) {
            if (p + 2 < 16) {
                int q = p + 2, s2 = q & 3;
                AH[s2][0] = Ah[(2 * q) * 32 + lane];
                AH[s2][1] = Ah[(2 * q + 1) * 32 + lane];
                AL[s2][0] = Al[(2 * q) * 32 + lane];
                AL[s2][1] = Al[(2 * q + 1) * 32 + lane];
            }
            int s = p & 3;
#pragma unroll
            for (int kk = 0; kk < 2; kk++) {
                int kc = 2 * p + kk;
                const char* bb = dsm + kc * 1024 + lane * 8;
#pragma unroll
                for (int nn = 0; nn < 4; nn++) {
                    uint2 bh = *(const uint2*)(bb + nn * 256);
                    uint2 bl = *(const uint2*)(bb + 32768 + nn * 256);
                    mma16816(acc[nn], &AH[s][kk].x, bh.x, bh.y);
                    mma16816(acc[nn], &AH[s][kk].x, bl.x, bl.y);
                    mma16816(acc[nn], &AL[s][kk].x, bh.x, bh.y);
                }
            }
        }

        // ---- store y transposed: g_yT[kz][batch][gate] ----
        {
            float* y0 = g_yT + (size_t)kz * Bb * NN;
            int r0 = nt * 128 + wid * 16 + (lane >> 2);
            int c0 = 2 * (lane & 3);
#pragma unroll
            for (int nn = 0; nn < 4; nn++) {
                int col = nn * 8 + c0;
                y0[(size_t)col * NN + r0] = acc[nn][0];
                y0[(size_t)(col + 1) * NN + r0] = acc[nn][1];
                y0[(size_t)col * NN + r0 + 8] = acc[nn][2];
                y0[(size_t)(col + 1) * NN + r0 + 8] = acc[nn][3];
            }
        }
        __threadfence();
        __syncthreads();
        if (tid == 0) {
            unsigned prev = atomicAdd(&g_ycnt, 1u);
            if (prev == (unsigned)(NCTA * (t + 1) - 1)) {
                __threadfence();
                g_yrel = (unsigned)(t + 1);
            }
        }

        // ---- epilogue on CTAs 0..31 (batch b) ----
        if (is_epi) {
            if (tid == 0) {
                while (g_yrel < (unsigned)(t + 1)) { }
                __threadfence();
            }
            __syncthreads();

            const float* y0 = g_yT + (size_t)b * NN;
            const float* y1 = g_yT + (size_t)(Bb + b) * NN;

            // batched y loads (high MLP)
            float yv[6][4];
#pragma unroll
            for (int g = 0; g < 6; g++)
#pragma unroll
                for (int k = 0; k < 4; k++) {
                    int j = tid + 256 * k + g * 1024;
                    yv[g][k] = y0[j] + y1[j];
                }

            // ---- part A: gates, h update, h repack ----
            float cpart = 0.f;
#pragma unroll
            for (int k = 0; k < 4; k++) {
                int j = tid + 256 * k;
                float r = fsigmoid(yv[0][k] + yv[3][k] + brr[k]);
                float z = fsigmoid(yv[1][k] + yv[4][k] + bzz[k]);
                float nv = ftanh(yv[2][k] + bni[k] + r * (yv[5][k] + bnh[k]));
                float hnew = (1.f - z) * nv + z * hreg[k];
                hreg[k] = hnew;
                __nv_bfloat16 hi, lo;
                bsplit(hnew, hi, lo);
                int kz2;
                uint32_t off = bfr_off(j, b, kz2);
                char* ph = g_bfr + 131072 + kz2 * 65536;
                *(unsigned short*)(ph + off) = __bfloat16_as_ushort(hi);
                *(unsigned short*)(ph + 32768 + off) = __bfloat16_as_ushort(lo);
                cpart = fmaf(v1r[k], hnew, cpart);
            }
            // release h: h-side GEMM CTAs start next step NOW
            __threadfence();
            __syncthreads();
            if (tid == 0) {
                unsigned prev = atomicAdd(&g_hcnt, 1u);
                if (prev == (unsigned)(Bb * (t + 1) - 1)) {
                    __threadfence();
                    g_hrel = (unsigned)(t + 1);
                }
            }

            // ---- part B: c reduce, scores, argmax, x gather/repack ----
#pragma unroll
            for (int o = 16; o > 0; o >>= 1) cpart += __shfl_xor_sync(0xFFFFFFFFu, cpart, o);
            if (lane == 0) red[wid] = cpart;
            __syncthreads();
            if (wid == 0) {
                float v = (lane < 8) ? red[lane] : 0.f;
#pragma unroll
                for (int o = 4; o > 0; o >>= 1) v += __shfl_xor_sync(0xFFFFFFFFu, v, o);
                if (lane == 0) red[0] = v;
            }
            __syncthreads();
            float c0 = red[0];

            float s0 = ftanh(c0 + areg0);
            float s1 = ftanh(c0 + areg1);
            float* pr = probs + ((size_t)b * Tt + t) * Ss;
            pr[tid] = s0;
            pr[tid + 256] = s1;
            float m0 = s0 + mk0;
            float m1 = s1 + mk1;
            float bv = m0;
            int bi = tid;
            if (m1 > bv) { bv = m1; bi = tid + 256; }
#pragma unroll
            for (int o = 16; o > 0; o >>= 1) {
                float v = __shfl_xor_sync(0xFFFFFFFFu, bv, o);
                int ii = __shfl_xor_sync(0xFFFFFFFFu, bi, o);
                if (v > bv || (v == bv && ii < bi)) { bv = v; bi = ii; }
            }
            if (lane == 0) { sv[wid] = bv; si[wid] = bi; }
            __syncthreads();
            if (wid == 0) {
                float v = (lane < 8) ? sv[lane] : -3.4e38f;
                int ii = (lane < 8) ? si[lane] : (1 << 30);
#pragma unroll
                for (int o = 4; o > 0; o >>= 1) {
                    float v2 = __shfl_xor_sync(0xFFFFFFFFu, v, o);
                    int i2 = __shfl_xor_sync(0xFFFFFFFFu, ii, o);
                    if (v2 > v || (v2 == v && i2 < ii)) { v = v2; ii = i2; }
                }
                if (lane == 0) si[0] = ii;
            }
            __syncthreads();
            int idx = si[0];
            const float* xr = inputs + ((size_t)b * Ss + idx) * Hh;
#pragma unroll
            for (int k = 0; k < 4; k++) {
                int j = tid + 256 * k;
                float xv = xr[j];
                __nv_bfloat16 hi, lo;
                bsplit(xv, hi, lo);
                int kz2;
                uint32_t off = bfr_off(j, b, kz2);
                char* px = g_bfr + kz2 * 65536;
                *(unsigned short*)(px + off) = __bfloat16_as_ushort(hi);
                *(unsigned short*)(px + 32768 + off) = __bfloat16_as_ushort(lo);
            }
            // release x: x-side GEMM CTAs start next step
            __threadfence();
            __syncthreads();
            if (tid == 0) {
                unsigned prev = atomicAdd(&g_xcnt, 1u);
                if (prev == (unsigned)(Bb * (t + 1) - 1)) {
                    __threadfence();
                    g_xrel = (unsigned)(t + 1);
                }
            }
        }
    }
}

// ===================== context (step-0 softmax) =====================
__global__ void __launch_bounds__(256) ctx_kernel(const float* __restrict__ inputs,
                                                  const float* __restrict__ mask,
                                                  const float* __restrict__ probs,
                                                  float* __restrict__ ctx) {
    const int b = blockIdx.x;
    const int hq = blockIdx.y;
    const int tid = threadIdx.x;
    __shared__ float p[Ss];
    __shared__ float red[256];

    for (int s = tid; s < Ss; s += 256)
        p[s] = probs[(size_t)b * Tt * Ss + s] + mask[b * Ss + s];
    __syncthreads();
    float m = -1e30f;
    for (int s = tid; s < Ss; s += 256) m = fmaxf(m, p[s]);
    red[tid] = m;
    __syncthreads();
    for (int st = 128; st >= 1; st >>= 1) {
        if (tid < st) red[tid] = fmaxf(red[tid], red[tid + st]);
        __syncthreads();
    }
    const float mx = red[0];
    __syncthreads();
    float sm = 0.f;
    for (int s = tid; s < Ss; s += 256) {
        float e = expf(p[s] - mx);
        p[s] = e;
        sm += e;
    }
    red[tid] = sm;
    __syncthreads();
    for (int st = 128; st >= 1; st >>= 1) {
        if (tid < st) red[tid] += red[tid + st];
        __syncthreads();
    }
    const float Z = red[0];
    __syncthreads();
    const int h = hq * 256 + tid;
    float acc = 0.f;
    for (int s = 0; s < Ss; s++)
        acc = fmaf(p[s], inputs[((size_t)b * Ss + s) * Hh + h], acc);
    ctx[b * Hh + h] = acc / Z;
}

// ===================== launch =====================
extern "C" void kernel_launch(void* const* d_in, const int* in_sizes, int n_in,
                              void* d_out, int out_size) {
    const float* inputs   = (const float*)d_in[0];
    const float* mask     = (const float*)d_in[1];
    // d_in[2] = inputs_embeds (unused, use_emb=False)
    const float* features = (const float*)d_in[3];
    const float* w_ih     = (const float*)d_in[4];
    const float* b_ih     = (const float*)d_in[5];
    const float* w_hh     = (const float*)d_in[6];
    const float* b_hh     = (const float*)d_in[7];
    const float* W1       = (const float*)d_in[8];
    const float* W2       = (const float*)d_in[9];
    const float* V        = (const float*)d_in[10];

    float* out   = (float*)d_out;
    float* probs = out;                            // [B, T, S]
    float* ctx   = out + (size_t)Bb * Tt * Ss;     // [B, H]

    cudaFuncSetAttribute(gru_persist, cudaFuncAttributeMaxDynamicSharedMemorySize, DSMEM);

    prep_pack_b<<<Bb, 256>>>(features);
    prep_v<<<8, 256>>>(W1, W2, V);
    prep_wfr<<<3072, 256>>>(w_ih, w_hh);
    prep_bias<<<NN / 1024, 1024>>>(b_ih, b_hh);
    prep_a<<<(Bb * Ss) / 8, 256>>>(inputs);

    gru_persist<<<NCTA, 256, DSMEM>>>(inputs, mask, probs);

    ctx_kernel<<<dim3(Bb, 4), 256>>>(inputs, mask, probs, ctx);
}